// round 6
// baseline (speedup 1.0000x reference)
#include <cuda_runtime.h>
#include <cuda_bf16.h>
#include <cstdint>

// FeatureBank: out = memory, except rows y[i] get normalize(0.5*memory[y[i]] + 0.5*x[i])
//
// Inputs: x [4096,128] f32, y [4096] int32, memory [500000,128] f32
// Output: new_memory [500000,128] f32
//
// Structure: SM streaming copy kernel + PDL-overlapped update kernel.
// The update kernel reads only inputs (memory, x, y) -> its loads/compute overlap
// the copy; only its 4096-row stores are ordered after the copy grid completes
// (cudaGridDependencySynchronize). WAW on dirty rows resolves update-last. Both
// kernels + PDL attribute are graph-capturable.

#define MOMENTUM 0.5f
#define DIM 128
#define BATCH 4096
#define N_ROWS 500000
#define N_FLOAT4 ((size_t)N_ROWS * DIM / 4)   // 16,000,000

#define COPY_BLOCKS 592     // 4 blocks/SM * 148 SMs -> leaves 4 slots/SM for update
#define COPY_THREADS 256
#define UPD_THREADS 256
#define UPD_BLOCKS (BATCH * 32 / UPD_THREADS) // 512, all co-resident during copy

__global__ void __launch_bounds__(COPY_THREADS) bank_copy_kernel(
        const float4* __restrict__ src, float4* __restrict__ dst) {
    // Let the dependent (update) kernel launch immediately.
    cudaTriggerProgrammaticLaunchCompletion();

    size_t stride = (size_t)gridDim.x * blockDim.x;
    size_t i = (size_t)blockIdx.x * blockDim.x + threadIdx.x;

    // 4-way unrolled grid-stride streaming copy (MLP=4, evict-first hints)
    for (; i + 3 * stride < N_FLOAT4; i += 4 * stride) {
        float4 a = __ldcs(src + i);
        float4 b = __ldcs(src + i + stride);
        float4 c = __ldcs(src + i + 2 * stride);
        float4 d = __ldcs(src + i + 3 * stride);
        __stcs(dst + i, a);
        __stcs(dst + i + stride, b);
        __stcs(dst + i + 2 * stride, c);
        __stcs(dst + i + 3 * stride, d);
    }
    for (; i < N_FLOAT4; i += stride)
        __stcs(dst + i, __ldcs(src + i));
}

// One warp per batch row. Loads+compute overlap the copy kernel; stores wait.
__global__ void __launch_bounds__(UPD_THREADS) featurebank_update_kernel(
        const float* __restrict__ x,
        const int* __restrict__ y,
        const float* __restrict__ memory,
        float* __restrict__ out) {
    int warp_id = (blockIdx.x * blockDim.x + threadIdx.x) >> 5;
    int lane = threadIdx.x & 31;

    int row = y[warp_id];

    const float4* xr = reinterpret_cast<const float4*>(x + (size_t)warp_id * DIM);
    const float4* mr = reinterpret_cast<const float4*>(memory + (size_t)row * DIM);

    float4 xv = xr[lane];
    float4 mv = mr[lane];

    float4 w;
    w.x = mv.x * MOMENTUM + xv.x * (1.0f - MOMENTUM);
    w.y = mv.y * MOMENTUM + xv.y * (1.0f - MOMENTUM);
    w.z = mv.z * MOMENTUM + xv.z * (1.0f - MOMENTUM);
    w.w = mv.w * MOMENTUM + xv.w * (1.0f - MOMENTUM);

    float ss = w.x * w.x + w.y * w.y + w.z * w.z + w.w * w.w;
    #pragma unroll
    for (int off = 16; off > 0; off >>= 1)
        ss += __shfl_xor_sync(0xFFFFFFFFu, ss, off);

    float inv = rsqrtf(ss);

    float4 o;
    o.x = w.x * inv;
    o.y = w.y * inv;
    o.z = w.z * inv;
    o.w = w.w * inv;

    // Wait for the copy grid to fully complete (WAW ordering on dirty rows),
    // then commit the 4096 updated rows.
    cudaGridDependencySynchronize();

    float4* orow = reinterpret_cast<float4*>(out + (size_t)row * DIM);
    orow[lane] = o;
}

extern "C" void kernel_launch(void* const* d_in, const int* in_sizes, int n_in,
                              void* d_out, int out_size) {
    const float* x      = (const float*)d_in[0];
    const int*   y      = (const int*)d_in[1];
    const float* memory = (const float*)d_in[2];
    float*       out    = (float*)d_out;

    // 1. Bulk streaming copy (fires programmatic-launch trigger at entry)
    bank_copy_kernel<<<COPY_BLOCKS, COPY_THREADS>>>(
        (const float4*)memory, (float4*)out);

    // 2. Update kernel with programmatic dependent launch: overlaps the copy,
    //    orders only its stores after the copy grid.
    cudaLaunchConfig_t cfg = {};
    cfg.gridDim = dim3(UPD_BLOCKS, 1, 1);
    cfg.blockDim = dim3(UPD_THREADS, 1, 1);
    cfg.dynamicSmemBytes = 0;
    cfg.stream = 0;
    cudaLaunchAttribute attrs[1];
    attrs[0].id = cudaLaunchAttributeProgrammaticStreamSerialization;
    attrs[0].val.programmaticStreamSerializationAllowed = 1;
    cfg.attrs = attrs;
    cfg.numAttrs = 1;
    cudaLaunchKernelEx(&cfg, featurebank_update_kernel, x, y, memory, out);
}

// round 10
// speedup vs baseline: 1.1093x; 1.1093x over previous
#include <cuda_runtime.h>
#include <cuda_bf16.h>
#include <cstdint>

// FeatureBank: out = memory, except rows y[i] get normalize(0.5*memory[y[i]] + 0.5*x[i])
//
// Inputs: x [4096,128] f32, y [4096] int32, memory [500000,128] f32
// Output: new_memory [500000,128] f32
//
// Graph topology (fork/join, all capturable):
//   stream0: memcpyAsync(out, memory, 256MB)        <- copy engine, 6.59 TB/s measured
//   stream2: compute_kernel -> g_staging (2MB)      <- overlaps the copy (reads inputs only)
//   stream0 (after both): commit_kernel             <- out[y[i]] = staging[i], short tail
//
// Static stream/events created lazily on first call (no device memory involved).

#define MOMENTUM 0.5f
#define DIM 128
#define BATCH 4096
#define N_ROWS 500000

__device__ float g_staging[BATCH * DIM];   // 2 MB scratch, module-scope (allowed)

// One warp per batch row: gather memory[y[i]], blend with x[i], normalize,
// store contiguously to staging. Runs concurrently with the bulk memcpy.
__global__ void __launch_bounds__(256) featurebank_compute_kernel(
        const float* __restrict__ x,
        const int* __restrict__ y,
        const float* __restrict__ memory) {
    int warp_id = (blockIdx.x * blockDim.x + threadIdx.x) >> 5;
    int lane = threadIdx.x & 31;

    int row = y[warp_id];

    const float4* xr = reinterpret_cast<const float4*>(x + (size_t)warp_id * DIM);
    const float4* mr = reinterpret_cast<const float4*>(memory + (size_t)row * DIM);

    float4 xv = xr[lane];
    float4 mv = mr[lane];

    float4 w;
    w.x = mv.x * MOMENTUM + xv.x * (1.0f - MOMENTUM);
    w.y = mv.y * MOMENTUM + xv.y * (1.0f - MOMENTUM);
    w.z = mv.z * MOMENTUM + xv.z * (1.0f - MOMENTUM);
    w.w = mv.w * MOMENTUM + xv.w * (1.0f - MOMENTUM);

    float ss = w.x * w.x + w.y * w.y + w.z * w.z + w.w * w.w;
    #pragma unroll
    for (int off = 16; off > 0; off >>= 1)
        ss += __shfl_xor_sync(0xFFFFFFFFu, ss, off);

    float inv = rsqrtf(ss);

    float4 o;
    o.x = w.x * inv;
    o.y = w.y * inv;
    o.z = w.z * inv;
    o.w = w.w * inv;

    reinterpret_cast<float4*>(g_staging + (size_t)warp_id * DIM)[lane] = o;
}

// Minimal post-copy tail: scatter staging rows into out.
__global__ void __launch_bounds__(256) featurebank_commit_kernel(
        const int* __restrict__ y,
        float* __restrict__ out) {
    int warp_id = (blockIdx.x * blockDim.x + threadIdx.x) >> 5;
    int lane = threadIdx.x & 31;

    int row = y[warp_id];   // independent of the staging load; both issue immediately
    float4 v = reinterpret_cast<const float4*>(g_staging + (size_t)warp_id * DIM)[lane];
    reinterpret_cast<float4*>(out + (size_t)row * DIM)[lane] = v;
}

extern "C" void kernel_launch(void* const* d_in, const int* in_sizes, int n_in,
                              void* d_out, int out_size) {
    const float* x      = (const float*)d_in[0];
    const int*   y      = (const int*)d_in[1];
    const float* memory = (const float*)d_in[2];
    float*       out    = (float*)d_out;

    size_t bank_bytes = (size_t)out_size * sizeof(float);   // 256 MB

    static cudaStream_t s2 = nullptr;
    static cudaEvent_t  e_fork = nullptr, e_join = nullptr;
    if (s2 == nullptr) {
        cudaStreamCreateWithFlags(&s2, cudaStreamNonBlocking);
        cudaEventCreateWithFlags(&e_fork, cudaEventDisableTiming);
        cudaEventCreateWithFlags(&e_join, cudaEventDisableTiming);
    }

    const int blocks = (BATCH * 32) / 256;   // 512

    // Fork: pull s2 into the captured graph, run compute concurrent with the copy.
    cudaEventRecord(e_fork, 0);
    cudaStreamWaitEvent(s2, e_fork, 0);
    featurebank_compute_kernel<<<blocks, 256, 0, s2>>>(x, y, memory);
    cudaEventRecord(e_join, s2);

    // Bulk copy on the main stream (dominant cost, near HBM roofline).
    cudaMemcpyAsync(out, memory, bank_bytes, cudaMemcpyDeviceToDevice, 0);

    // Join, then the short commit tail.
    cudaStreamWaitEvent(0, e_join, 0);
    featurebank_commit_kernel<<<blocks, 256>>>(y, out);
}

// round 11
// speedup vs baseline: 1.2110x; 1.0917x over previous
#include <cuda_runtime.h>
#include <cuda_bf16.h>
#include <cstdint>

// FeatureBank: out = memory, except rows y[i] get normalize(0.5*memory[y[i]] + 0.5*x[i])
//
// Inputs: x [4096,128] f32, y [4096] int32, memory [500000,128] f32
// Output: new_memory [500000,128] f32
//
// Two nodes, PDL-chained:
//   1. scatter (primary):  map[y[i]] = i+1                    (~1-2us, hidden under #2's prelude)
//   2. fused   (secondary): streaming copy of all rows; each warp issues its
//      memory loads, then cudaGridDependencySynchronize(), then reads the map.
//      Dirty rows take the blend+normalize path and self-reset map[row]=0.
//
// Map invariant: all-zero outside a call (zero-init .bss, restored in-line).

#define MOMENTUM 0.5f
#define DIM 128
#define BATCH 4096
#define N_ROWS 500000

#define FUSED_THREADS 256
#define ROWS_PER_WARP 2
// 500000 rows / 2 rows/warp = 250000 warps / 8 warps/block = 31250 blocks
#define FUSED_BLOCKS (N_ROWS / ROWS_PER_WARP / (FUSED_THREADS / 32))

__device__ int g_row_map[N_ROWS];  // 2 MB, zero-initialized

__global__ void scatter_map_kernel(const int* __restrict__ y) {
    int i = blockIdx.x * blockDim.x + threadIdx.x;
    if (i < BATCH) g_row_map[y[i]] = i + 1;
}

__device__ __forceinline__ void process_row(int row, int lane, float4 mv,
                                            const float* __restrict__ x,
                                            float* __restrict__ out,
                                            int m) {
    float4* dst = reinterpret_cast<float4*>(out + (size_t)row * DIM);
    if (m == 0) {
        __stcs(dst + lane, mv);
    } else {
        const float4* xr = reinterpret_cast<const float4*>(x + (size_t)(m - 1) * DIM);
        float4 xv = xr[lane];

        float4 w;
        w.x = mv.x * MOMENTUM + xv.x * (1.0f - MOMENTUM);
        w.y = mv.y * MOMENTUM + xv.y * (1.0f - MOMENTUM);
        w.z = mv.z * MOMENTUM + xv.z * (1.0f - MOMENTUM);
        w.w = mv.w * MOMENTUM + xv.w * (1.0f - MOMENTUM);

        float ss = w.x * w.x + w.y * w.y + w.z * w.z + w.w * w.w;
        #pragma unroll
        for (int off = 16; off > 0; off >>= 1)
            ss += __shfl_xor_sync(0xFFFFFFFFu, ss, off);

        float inv = rsqrtf(ss);

        float4 o;
        o.x = w.x * inv;
        o.y = w.y * inv;
        o.z = w.z * inv;
        o.w = w.w * inv;
        dst[lane] = o;

        if (lane == 0) g_row_map[row] = 0;  // self-reset for the next call
    }
}

__global__ void __launch_bounds__(FUSED_THREADS) fused_copy_update_kernel(
        const float* __restrict__ x,
        const float* __restrict__ memory,
        float* __restrict__ out) {
    int warp_id = (blockIdx.x * blockDim.x + threadIdx.x) >> 5;
    int lane = threadIdx.x & 31;

    int r0 = warp_id * ROWS_PER_WARP;
    int r1 = r0 + 1;

    // Issue both streaming loads before waiting on the scatter grid (overlap).
    const float4* s0 = reinterpret_cast<const float4*>(memory + (size_t)r0 * DIM);
    const float4* s1 = reinterpret_cast<const float4*>(memory + (size_t)r1 * DIM);
    float4 mv0 = __ldcs(s0 + lane);
    float4 mv1 = __ldcs(s1 + lane);

    // Wait for scatter (primary grid) to complete before reading the map.
    cudaGridDependencySynchronize();

    int m01 = 0;
    if (lane < 2) m01 = g_row_map[r0 + lane];
    int m0 = __shfl_sync(0xFFFFFFFFu, m01, 0);
    int m1 = __shfl_sync(0xFFFFFFFFu, m01, 1);

    process_row(r0, lane, mv0, x, out, m0);
    process_row(r1, lane, mv1, x, out, m1);
}

extern "C" void kernel_launch(void* const* d_in, const int* in_sizes, int n_in,
                              void* d_out, int out_size) {
    const float* x      = (const float*)d_in[0];
    const int*   y      = (const int*)d_in[1];
    const float* memory = (const float*)d_in[2];
    float*       out    = (float*)d_out;

    // 1. mark dirty rows (primary)
    scatter_map_kernel<<<(BATCH + 255) / 256, 256>>>(y);

    // 2. fused streaming copy + update (secondary, PDL: overlaps scatter's tail)
    cudaLaunchConfig_t cfg = {};
    cfg.gridDim = dim3(FUSED_BLOCKS, 1, 1);
    cfg.blockDim = dim3(FUSED_THREADS, 1, 1);
    cfg.dynamicSmemBytes = 0;
    cfg.stream = 0;
    cudaLaunchAttribute attrs[1];
    attrs[0].id = cudaLaunchAttributeProgrammaticStreamSerialization;
    attrs[0].val.programmaticStreamSerializationAllowed = 1;
    cfg.attrs = attrs;
    cfg.numAttrs = 1;
    cudaLaunchKernelEx(&cfg, fused_copy_update_kernel, x, memory, out);
}